// round 7
// baseline (speedup 1.0000x reference)
#include <cuda_runtime.h>
#include <cstdint>

static constexpr int T_IN  = 1048576;
static constexpr int T_OUT = 1048564;              // T_IN - 12
static constexpr int ROWS  = 32;                   // 8 * 4
static constexpr int VEC_PER_ROW = T_OUT / 4;      // 262141 output float4s per row
static constexpr int F4_PER_ROW  = T_IN / 4;       // 262144 input float4s per row
static constexpr long TOTAL_F4   = (long)ROWS * F4_PER_ROW;   // 8388608
static constexpr int VEC_TILE = 512;               // output float4s per tile
static constexpr int NTILES = ROWS * 512;          // 16384 tiles
static constexpr int TILE_F4 = 515;                // input float4s per tile (12-float halo)
static constexpr int TPB = 3;                      // tiles per block
static constexpr int GRID3 = (NTILES + TPB - 1) / TPB;   // 5462

__global__ __launch_bounds__(256)
void conv13_tri(const float4* __restrict__ x4, float* __restrict__ out,
                const float* __restrict__ fd, const float* __restrict__ gauss) {
    __shared__ float4 sx[TPB][TILE_F4 + 1];
    __shared__ float sc[13];

    const int t = threadIdx.x;

    uint32_t sb[TPB];
    #pragma unroll
    for (int i = 0; i < TPB; ++i)
        asm("{ .reg .u64 a; cvta.to.shared.u64 a, %1; cvt.u32.u64 %0, a; }"
            : "=r"(sb[i]) : "l"(&sx[i][0]));

    auto prefetch = [&](int tid, uint32_t s0) {
        int row  = tid >> 9;
        int tile = tid & 511;
        long gbase = (long)row * F4_PER_ROW + (long)tile * VEC_TILE;
        #pragma unroll
        for (int r = 0; r < 2; ++r) {
            int i = t + r * 256;
            long g4 = gbase + i;
            int sz = (g4 < TOTAL_F4) ? 16 : 0;     // zero-fill past end of x
            asm volatile("cp.async.cg.shared.global [%0], [%1], 16, %2;"
                         :: "r"(s0 + i * 16), "l"(x4 + g4), "r"(sz));
        }
        if (t < TILE_F4 - 512) {                   // i = 512..514
            int i = 512 + t;
            long g4 = gbase + i;
            int sz = (g4 < TOTAL_F4) ? 16 : 0;
            asm volatile("cp.async.cg.shared.global [%0], [%1], 16, %2;"
                         :: "r"(s0 + i * 16), "l"(x4 + g4), "r"(sz));
        }
    };

    const int base = blockIdx.x * TPB;

    // Put all three tiles' loads in flight immediately (3 commit groups).
    #pragma unroll
    for (int i = 0; i < TPB; ++i) {
        if (base + i < NTILES) prefetch(base + i, sb[i]);
        asm volatile("cp.async.commit_group;");
    }

    // Compose the 13-tap composite kernel while copies fly.
    if (t < 13) {
        float acc = 0.0f;
        #pragma unroll
        for (int i = 0; i < 5; ++i) {
            int j = t - i;
            if (j >= 0 && j < 9) acc = fmaf(__ldg(fd + i), __ldg(gauss + j), acc);
        }
        sc[t] = acc;
    }

    auto compute = [&](int tid, const float4* __restrict__ buf) {
        const int row  = tid >> 9;
        const int tile = tid & 511;
        const int vb   = tile * VEC_TILE;
        #pragma unroll
        for (int r = 0; r < 2; ++r) {
            int v = t + r * 256;
            int gvec = vb + v;

            float4 q0 = buf[v], q1 = buf[v + 1], q2 = buf[v + 2], q3 = buf[v + 3];
            float xv[16] = {q0.x, q0.y, q0.z, q0.w,  q1.x, q1.y, q1.z, q1.w,
                            q2.x, q2.y, q2.z, q2.w,  q3.x, q3.y, q3.z, q3.w};

            float y0 = 0.f, y1 = 0.f, y2 = 0.f, y3 = 0.f;
            #pragma unroll
            for (int k = 0; k < 13; ++k) {
                float c = sc[k];
                y0 = fmaf(c, xv[k],     y0);
                y1 = fmaf(c, xv[k + 1], y1);
                y2 = fmaf(c, xv[k + 2], y2);
                y3 = fmaf(c, xv[k + 3], y3);
            }

            if (gvec < VEC_PER_ROW) {
                long o = (long)row * T_OUT + (long)gvec * 4;
                __stcs(reinterpret_cast<float4*>(out + o),
                       make_float4(y0, y1, y2, y3));
            }
        }
    };

    asm volatile("cp.async.wait_group 2;");   // tile0 resident (t1,t2 in flight)
    __syncthreads();
    if (base + 0 < NTILES) compute(base + 0, sx[0]);

    asm volatile("cp.async.wait_group 1;");   // tile1 resident (t2 in flight)
    __syncthreads();
    if (base + 1 < NTILES) compute(base + 1, sx[1]);

    asm volatile("cp.async.wait_group 0;");   // tile2 resident
    __syncthreads();
    if (base + 2 < NTILES) compute(base + 2, sx[2]);
}

extern "C" void kernel_launch(void* const* d_in, const int* in_sizes, int n_in,
                              void* d_out, int out_size) {
    const float4* x4   = (const float4*)d_in[0];
    const float* fd    = (const float*)d_in[1];
    const float* gauss = (const float*)d_in[2];
    float* out = (float*)d_out;

    conv13_tri<<<GRID3, 256>>>(x4, out, fd, gauss);
}